// round 3
// baseline (speedup 1.0000x reference)
#include <cuda_runtime.h>
#include <cuda_bf16.h>

// RotaryPositionEncoding3D: out[B,N,192,2] f32 from xyz[B,N,3] f32 and div_term[32] f32.
// Each output float4 g = (cos, sin, cos, sin) of angle xyz[p, axis]*div_term[bin],
//   p = g/96, j = g%96, axis = j%3, bin = j/3.
//
// v3: 8 float4s per thread at stride-256 within a 2048-float4 block tile.
//  - 8 independent STG.128 in flight per warp (v2 had 4; DRAM busy 73.4%)
//  - incremental (p, j) update: stride 256 = 2*96 + 64, so one /96 per thread
//    instead of one per k (v2 alu pipe was 20.1% from repeated reciprocal-mul)
//  - streaming stores (__stcs): write-once output, keep L2 for xyz broadcasts
// 402.6 MB stored; purely HBM-write-bound.

#define F4_PER_THREAD 8
#define THREADS 256
#define TILE (THREADS * F4_PER_THREAD)   // 2048 float4 per block

__global__ void __launch_bounds__(THREADS)
rope3d_kernel(const float* __restrict__ xyz,
              const float* __restrict__ div_term,
              float4* __restrict__ out,
              int total_f4) {
    const int base = blockIdx.x * TILE + threadIdx.x;

    // One division for the whole thread; then advance (p, j) incrementally.
    unsigned p = (unsigned)base / 96u;
    unsigned j = (unsigned)base - p * 96u;   // j = 3*bin + axis

    float c[F4_PER_THREAD], s[F4_PER_THREAD];

    unsigned pk = p, jk = j;
#pragma unroll
    for (int k = 0; k < F4_PER_THREAD; ++k) {
        unsigned bin  = jk / 3u;             // small-const div: 2 IMADs
        unsigned axis = jk - bin * 3u;

        float x  = __ldg(&xyz[pk * 3u + axis]);
        float dt = __ldg(&div_term[bin]);
        __sincosf(x * dt, &s[k], &c[k]);     // |ang| <= 1, MUFU precision ample

        // advance by THREADS=256 = 2*96 + 64
        pk += 2u;
        jk += 64u;
        if (jk >= 96u) { jk -= 96u; ++pk; }
    }

#pragma unroll
    for (int k = 0; k < F4_PER_THREAD; ++k) {
        int g = base + k * THREADS;
        if (g < total_f4)
            __stcs(&out[g], make_float4(c[k], s[k], c[k], s[k]));
    }
}

extern "C" void kernel_launch(void* const* d_in, const int* in_sizes, int n_in,
                              void* d_out, int out_size) {
    const float* xyz      = (const float*)d_in[0];
    const float* div_term = (const float*)d_in[1];
    float4* out = (float4*)d_out;

    int total_f4 = out_size / 4;                     // 25,165,824 for B=4, N=65536
    int blocks = (total_f4 + TILE - 1) / TILE;       // 12,288 (exact fit)
    rope3d_kernel<<<blocks, THREADS>>>(xyz, div_term, out, total_f4);
}

// round 4
// speedup vs baseline: 1.3831x; 1.3831x over previous
#include <cuda_runtime.h>
#include <cuda_bf16.h>

// RotaryPositionEncoding3D: out[B,N,192,2] f32 from xyz[B,N,3] f32 and div_term[32] f32.
// Each output float4 g = (cos, sin, cos, sin) of angle xyz[p, axis]*div_term[bin],
//   p = g/96, j = g%96, axis = j%3, bin = j/3.
//
// v4: 8 float4s/thread at stride-256 (TILE=2048/block), with per-k indices in
// CLOSED FORM (no loop-carried state). v3's incremental update serialized the
// 8 LDG chains (address k depended on k-1) and collapsed memory-level
// parallelism (DRAM 73%->54%). Here every k's address derives independently
// from (p0, j0): t = j0 + k*256 < 1888, dp = t/96, jk = t%96 -- the compiler
// front-batches all 8 LDG+MUFU chains, then bursts 8 STG.128.
// 402.6 MB stored; HBM-write-bound.

#define F4_PER_THREAD 8
#define THREADS 256
#define TILE (THREADS * F4_PER_THREAD)   // 2048 float4 per block

__global__ void __launch_bounds__(THREADS)
rope3d_kernel(const float* __restrict__ xyz,
              const float* __restrict__ div_term,
              float4* __restrict__ out,
              int total_f4) {
    const int base = blockIdx.x * TILE + threadIdx.x;

    const unsigned p0 = (unsigned)base / 96u;
    const unsigned j0 = (unsigned)base - p0 * 96u;   // [0, 96)

    float c[F4_PER_THREAD], s[F4_PER_THREAD];

#pragma unroll
    for (int k = 0; k < F4_PER_THREAD; ++k) {
        // Independent per-k index math: t < 96 + 7*256 = 1888
        unsigned t    = j0 + (unsigned)(k * THREADS);
        unsigned dp   = t / 96u;                     // small-range const div
        unsigned jk   = t - dp * 96u;                // j = 3*bin + axis
        unsigned bin  = jk / 3u;
        unsigned axis = jk - bin * 3u;

        float x  = __ldg(&xyz[(p0 + dp) * 3u + axis]);
        float dt = __ldg(&div_term[bin]);
        __sincosf(x * dt, &s[k], &c[k]);             // |ang| <= 1, ample precision
    }

#pragma unroll
    for (int k = 0; k < F4_PER_THREAD; ++k) {
        int g = base + k * THREADS;
        if (g < total_f4)
            __stcs(&out[g], make_float4(c[k], s[k], c[k], s[k]));
    }
}

extern "C" void kernel_launch(void* const* d_in, const int* in_sizes, int n_in,
                              void* d_out, int out_size) {
    const float* xyz      = (const float*)d_in[0];
    const float* div_term = (const float*)d_in[1];
    float4* out = (float4*)d_out;

    int total_f4 = out_size / 4;                     // 25,165,824 for B=4, N=65536
    int blocks = (total_f4 + TILE - 1) / TILE;       // 12,288 (exact fit)
    rope3d_kernel<<<blocks, THREADS>>>(xyz, div_term, out, total_f4);
}